// round 6
// baseline (speedup 1.0000x reference)
#include <cuda_runtime.h>
#include <cuda_bf16.h>
#include <math.h>
#include <stdint.h>

// ---------------- problem constants ----------------
#define BATCH   64
#define RESO    28
#define NTOK    784
#define DIMC    384
#define CBR     192
#define HEADS   8
#define CHH     24
#define WIN     196
#define GPB     32
#define HID     1536
#define MTOK    (BATCH*NTOK)   // 50176
#define MGEN    (BATCH*GPB)    // 2048
#define KGEN    392
#define KGENP   416
#define NGEN    38416

typedef __nv_bfloat16 bf16;
typedef __nv_bfloat162 bf162;

// ---------------- scratch ----------------
__device__ __align__(16) float g_an[(size_t)MTOK*DIMC];
__device__ __align__(16) bf16  g_wv0[(size_t)MGEN*KGENP];
__device__ __align__(16) bf16  g_wv1[(size_t)MGEN*KGENP];
__device__ __align__(16) bf16  g_logits[(size_t)MGEN*NGEN];
__device__ __align__(16) bf16  g_attn[(size_t)MTOK*DIMC];
__device__ __align__(16) float g_xmid[(size_t)MTOK*DIMC];
__device__ __align__(16) bf16  g_mn[(size_t)MTOK*DIMC];
__device__ __align__(16) bf16  g_h[(size_t)MTOK*HID];
// bf16 weights (g_bw* are column-permuted to t-major)
__device__ __align__(16) bf16  g_bw0[(size_t)KGEN*NGEN];
__device__ __align__(16) bf16  g_bw1[(size_t)KGEN*NGEN];
__device__ __align__(16) bf16  g_bpw[(size_t)DIMC*DIMC];
__device__ __align__(16) bf16  g_bf1[(size_t)DIMC*HID];
__device__ __align__(16) bf16  g_bf2[(size_t)HID*DIMC];
__device__ __align__(16) float g_gbp0[NGEN];
__device__ __align__(16) float g_gbp1[NGEN];

// ---------------- helpers ----------------
__device__ __forceinline__ uint32_t smem_u32(const void* p) {
    uint32_t a;
    asm("{ .reg .u64 t; cvta.to.shared.u64 t, %1; cvt.u32.u64 %0, t; }" : "=r"(a) : "l"(p));
    return a;
}
__device__ __forceinline__ void cp16(uint32_t d, const void* s, uint32_t sz) {
    asm volatile("cp.async.cg.shared.global [%0], [%1], 16, %2;" :: "r"(d), "l"(s), "r"(sz));
}
#define CP_COMMIT() asm volatile("cp.async.commit_group;" ::: "memory")
#define CP_WAIT(n)  asm volatile("cp.async.wait_group %0;" :: "n"(n) : "memory")

__device__ __forceinline__ void mma16(float* d, const uint32_t* a, const uint32_t* b) {
    asm volatile(
        "mma.sync.aligned.m16n8k16.row.col.f32.bf16.bf16.f32 "
        "{%0,%1,%2,%3},{%4,%5,%6,%7},{%8,%9},{%0,%1,%2,%3};"
        : "+f"(d[0]), "+f"(d[1]), "+f"(d[2]), "+f"(d[3])
        : "r"(a[0]), "r"(a[1]), "r"(a[2]), "r"(a[3]), "r"(b[0]), "r"(b[1]));
}
__device__ __forceinline__ void ldsm4(uint32_t* r, uint32_t addr) {
    asm volatile("ldmatrix.sync.aligned.m8n8.x4.shared.b16 {%0,%1,%2,%3}, [%4];"
        : "=r"(r[0]), "=r"(r[1]), "=r"(r[2]), "=r"(r[3]) : "r"(addr));
}
__device__ __forceinline__ void ldsm4t(uint32_t* r, uint32_t addr) {
    asm volatile("ldmatrix.sync.aligned.m8n8.x4.trans.shared.b16 {%0,%1,%2,%3}, [%4];"
        : "=r"(r[0]), "=r"(r[1]), "=r"(r[2]), "=r"(r[3]) : "r"(addr));
}

template <typename T>
__device__ __forceinline__ void st2(T* C, size_t idx, float v0, float v1);
template <>
__device__ __forceinline__ void st2<float>(float* C, size_t idx, float v0, float v1) {
    *(float2*)(C + idx) = make_float2(v0, v1);
}
template <>
__device__ __forceinline__ void st2<bf16>(bf16* C, size_t idx, float v0, float v1) {
    *(bf162*)(C + idx) = __floats2bfloat162_rn(v0, v1);
}

// ---------------- fp32 -> bf16 weight convert (plain) ----------------
__global__ void kcvt(const float* __restrict__ s, bf16* __restrict__ d, int n4) {
    int i = blockIdx.x * blockDim.x + threadIdx.x;
    if (i < n4) {
        float4 f = ((const float4*)s)[i];
        bf162* dd = (bf162*)d;
        dd[i * 2]     = __floats2bfloat162_rn(f.x, f.y);
        dd[i * 2 + 1] = __floats2bfloat162_rn(f.z, f.w);
    }
}

// ---------------- generate-weight convert + column permute (s,t)->(t,s) ----------------
__global__ void kcvtp(const float* __restrict__ W, bf16* __restrict__ Wp) {
    __shared__ float tile[32][33];
    int k = blockIdx.z;
    int s0 = blockIdx.y * 32, t0 = blockIdx.x * 32;
    int tx = threadIdx.x, ty = threadIdx.y; // 32 x 8
    const float* src = W + (size_t)k * NGEN;
    bf16* dst = Wp + (size_t)k * NGEN;
    for (int i = ty; i < 32; i += 8) {
        int s = s0 + i, t = t0 + tx;
        tile[i][tx] = (s < WIN && t < WIN) ? src[s * WIN + t] : 0.0f;
    }
    __syncthreads();
    for (int i = ty; i < 32; i += 8) {
        int t = t0 + i, s = s0 + tx;
        if (t < WIN && s < WIN)
            dst[t * WIN + s] = __float2bfloat16(tile[tx][i]);
    }
}

// ---------------- bias permute ----------------
__global__ void kpbias(const float* __restrict__ b, float* __restrict__ bp) {
    int i = blockIdx.x * blockDim.x + threadIdx.x;
    if (i < NGEN) {
        int t = i / WIN, s = i % WIN;
        bp[i] = b[s * WIN + t];
    }
}

// ---------------- fused center-norm1 + compress ----------------
__global__ __launch_bounds__(128) void knormc(
    const float* __restrict__ x, const float* __restrict__ w, const float* __restrict__ bb,
    const float* __restrict__ c0w, const float* __restrict__ c0b,
    const float* __restrict__ c1w, const float* __restrict__ c1b,
    float* __restrict__ an, bf16* __restrict__ wv0, bf16* __restrict__ wv1) {
    int tok = blockIdx.x;
    int b = tok / NTOK, n = tok % NTOK;
    const float* xr = x + (size_t)tok * DIMC;
    float* orow = an + (size_t)tok * DIMC;
    int tid = threadIdx.x;
    __shared__ float xs[DIMC];
    __shared__ float red[4];
    __shared__ float partial[4][32];

    float v0 = xr[tid], v1 = xr[tid + 128], v2 = xr[tid + 256];
    float s = v0 + v1 + v2;
#pragma unroll
    for (int o = 16; o > 0; o >>= 1) s += __shfl_xor_sync(0xffffffffu, s, o);
    if ((tid & 31) == 0) red[tid >> 5] = s;
    __syncthreads();
    float u = (red[0] + red[1] + red[2] + red[3]) * (1.0f / DIMC);
    const float sc = (float)DIMC / (float)(DIMC - 1);
    float o0 = w[tid]       * (sc * (v0 - u)) + bb[tid];
    float o1 = w[tid + 128] * (sc * (v1 - u)) + bb[tid + 128];
    float o2 = w[tid + 256] * (sc * (v2 - u)) + bb[tid + 256];
    orow[tid] = o0; orow[tid + 128] = o1; orow[tid + 256] = o2;
    xs[tid] = o0; xs[tid + 128] = o1; xs[tid + 256] = o2;
    __syncthreads();

    // 32 outputs (16 per branch), 4 k-chunks of 48
    int o = tid & 31, chunk = tid >> 5;
    int branch = o >> 4, j = o & 15;
    const float* cw = branch ? c1w : c0w;
    const float* xb = xs + branch * CBR;
    float acc = 0.0f;
    int k0 = chunk * 48;
#pragma unroll 4
    for (int k = k0; k < k0 + 48; k++) acc = fmaf(xb[k], cw[k * 16 + j], acc);
    partial[chunk][o] = acc;
    __syncthreads();
    if (tid < 32) {
        int oo = tid;
        int br = oo >> 4, jj = oo & 15;
        float sum = partial[0][oo] + partial[1][oo] + partial[2][oo] + partial[3][oo]
                  + (br ? c1b[jj] : c0b[jj]);
        int head = jj >> 1, di = jj & 1;
        int row = n / RESO, col = n % RESO;
        int g, ss;
        if (br == 0) { int n2i = col / 7; g = n2i * HEADS + head; ss = row * 7 + col % 7; }
        else         { int n1i = row / 7; g = n1i * HEADS + head; ss = (row % 7) * 28 + col; }
        bf16* dst = br ? wv1 : wv0;
        dst[(size_t)(b * GPB + g) * KGENP + ss * 2 + di] = __float2bfloat16(sum);
    }
}

__global__ void kpad(bf16* __restrict__ wv0, bf16* __restrict__ wv1) {
    int r = blockIdx.x, t = threadIdx.x;
    if (t < KGENP - KGEN) {
        wv0[(size_t)r * KGENP + KGEN + t] = __float2bfloat16(0.0f);
        wv1[(size_t)r * KGENP + KGEN + t] = __float2bfloat16(0.0f);
    }
}

// ---------------- center norm (stage 2) ----------------
template <typename OUTT>
__global__ void knorm(const float* __restrict__ x, const float* __restrict__ w,
                      const float* __restrict__ bb, OUTT* __restrict__ out) {
    int t = blockIdx.x;
    const float* xr = x + (size_t)t * DIMC;
    OUTT* orow = out + (size_t)t * DIMC;
    int tid = threadIdx.x; // 128
    float v0 = xr[tid], v1 = xr[tid + 128], v2 = xr[tid + 256];
    float s = v0 + v1 + v2;
#pragma unroll
    for (int o = 16; o > 0; o >>= 1) s += __shfl_xor_sync(0xffffffffu, s, o);
    __shared__ float red[4];
    if ((tid & 31) == 0) red[tid >> 5] = s;
    __syncthreads();
    float u = (red[0] + red[1] + red[2] + red[3]) * (1.0f / DIMC);
    const float sc = (float)DIMC / (float)(DIMC - 1);
    orow[tid]       = (OUTT)(w[tid]       * (sc * (v0 - u)) + bb[tid]);
    orow[tid + 128] = (OUTT)(w[tid + 128] * (sc * (v1 - u)) + bb[tid + 128]);
    orow[tid + 256] = (OUTT)(w[tid + 256] * (sc * (v2 - u)) + bb[tid + 256]);
}

// ---------------- bf16 mma.sync GEMM, 3-stage cp.async pipeline ----------------
template <int EPI, typename OUTT>
__global__ __launch_bounds__(256, 2) void tgemm(
    const bf16* __restrict__ A, const bf16* __restrict__ B,
    const float* __restrict__ bias, const float* __restrict__ res,
    const float* __restrict__ alpha, OUTT* __restrict__ C,
    int lda, int Kreal, int NC) {
    __shared__ bf16 As[3][128][40];
    __shared__ bf16 Bs[3][32][136];

    int tid = threadIdx.x;
    int w = tid >> 5, lane = tid & 31;
    int warpM = w >> 2, warpN = w & 3;
    int lr = lane >> 2, lc = lane & 3;
    int row0 = blockIdx.y * 128, col0 = blockIdx.x * 128;
    const int S = lda / 32;

    float acc[4][4][4];
#pragma unroll
    for (int a = 0; a < 4; a++)
#pragma unroll
        for (int bq = 0; bq < 4; bq++)
#pragma unroll
            for (int cq = 0; cq < 4; cq++) acc[a][bq][cq] = 0.0f;

    auto load_stage = [&](int s, int buf) {
        int s32 = s * 32;
#pragma unroll
        for (int i = 0; i < 2; i++) {
            int idx = tid + i * 256;
            int r = idx >> 2, c = idx & 3;
            cp16(smem_u32(&As[buf][r][c * 8]),
                 A + (size_t)(row0 + r) * lda + s32 + c * 8, 16u);
        }
#pragma unroll
        for (int i = 0; i < 2; i++) {
            int idx = tid + i * 256;
            int k = idx >> 4, c = idx & 15;
            int krow = s32 + k, gc = col0 + c * 8;
            bool val = (krow < Kreal) && (gc < NC);
            const bf16* sp = val ? (B + (size_t)krow * NC + gc) : B;
            cp16(smem_u32(&Bs[buf][k][c * 8]), sp, val ? 16u : 0u);
        }
    };

    load_stage(0, 0); CP_COMMIT();
    if (S > 1) load_stage(1, 1);
    CP_COMMIT();

    for (int s = 0; s < S; s++) {
        int cur = s % 3;
        CP_WAIT(1);
        __syncthreads();

#pragma unroll
        for (int ks = 0; ks < 2; ks++) {
            uint32_t ar[4][4];
            uint32_t br[4][2];
            int m = lane >> 3;
            int rA8 = (m & 1) * 8 + (lane & 7);
            int cA = ks * 16 + (m >> 1) * 8;
#pragma unroll
            for (int mt = 0; mt < 4; mt++)
                ldsm4(ar[mt], smem_u32(&As[cur][warpM * 64 + mt * 16 + rA8][cA]));
            int kB = ks * 16 + ((lane >> 3) & 1) * 8 + (lane & 7);
            int nB8 = (lane >> 4) * 8;
#pragma unroll
            for (int np = 0; np < 2; np++) {
                uint32_t rr[4];
                ldsm4t(rr, smem_u32(&Bs[cur][kB][warpN * 32 + np * 16 + nB8]));
                br[np * 2][0] = rr[0]; br[np * 2][1] = rr[1];
                br[np * 2 + 1][0] = rr[2]; br[np * 2 + 1][1] = rr[3];
            }
#pragma unroll
            for (int mt = 0; mt < 4; mt++)
#pragma unroll
                for (int nt = 0; nt < 4; nt++)
                    mma16(acc[mt][nt], ar[mt], br[nt]);
        }
        if (s + 2 < S) load_stage(s + 2, (s + 2) % 3);
        CP_COMMIT();
    }

    // epilogue
#pragma unroll
    for (int mt = 0; mt < 4; mt++) {
#pragma unroll
        for (int nt = 0; nt < 4; nt++) {
            int cbase = col0 + warpN * 32 + nt * 8 + lc * 2;
            if (cbase >= NC) continue;
            float bi0 = bias[cbase], bi1 = bias[cbase + 1];
            float al0 = 0.f, al1 = 0.f;
            if (EPI == 2) { al0 = alpha[cbase]; al1 = alpha[cbase + 1]; }
#pragma unroll
            for (int hh = 0; hh < 2; hh++) {
                int r = row0 + warpM * 64 + mt * 16 + lr + hh * 8;
                float v0 = acc[mt][nt][hh * 2]     + bi0;
                float v1 = acc[mt][nt][hh * 2 + 1] + bi1;
                size_t idx = (size_t)r * NC + cbase;
                if (EPI == 1) {
                    v0 = 0.5f * v0 * (1.0f + erff(v0 * 0.70710678118654752f));
                    v1 = 0.5f * v1 * (1.0f + erff(v1 * 0.70710678118654752f));
                }
                if (EPI == 2) {
                    float2 rr = *(const float2*)(res + idx);
                    v0 = rr.x + al0 * v0;
                    v1 = rr.y + al1 * v1;
                }
                st2<OUTT>(C, idx, v0, v1);
            }
        }
    }
}

// ---------------- fused softmax + V@W + scatter (t-major logits) ----------------
// logits'[bg][t*196+s]; softmax over contiguous s; out[c][t] = sum_s v[c][s]*p[t][s]
__global__ __launch_bounds__(384, 2) void kmix(const bf16* __restrict__ logits,
                                               const float* __restrict__ an,
                                               bf16* __restrict__ attn, int branch) {
    extern __shared__ char smb[];
    bf16* p  = (bf16*)smb;                       // [196][196]
    bf16* v  = (bf16*)(smb + WIN * WIN * 2);     // [24][196]
    float* sInv = (float*)(smb + (WIN * WIN + CHH * WIN) * 2);

    int bg = blockIdx.x;
    int b = bg / GPB, g = bg % GPB;
    int head = g % HEADS, wi = g / HEADS;
    int coff = branch * CBR + head * CHH;
    int tid = threadIdx.x;

    // copy logits row (38416 bf16 = 4802 uint4), contiguous
    {
        const uint4* src = (const uint4*)(logits + (size_t)bg * NGEN);
        uint4* pd = (uint4*)p;
        for (int i = tid; i < NGEN / 8; i += 384) pd[i] = src[i];
    }
    // v gather (bf16)
    for (int i = tid; i < CHH * WIN; i += 384) {
        int ch = i / WIN, s = i % WIN;
        int n;
        if (branch == 0) { int h = s / 7, ww = s % 7; n = h * RESO + wi * 7 + ww; }
        else             { int h = s / 28, ww = s % 28; n = (wi * 7 + h) * RESO + ww; }
        v[ch * WIN + s] = __float2bfloat16(an[((size_t)b * NTOK + n) * DIMC + coff + ch]);
    }
    __syncthreads();

    // softmax: warp per row t (12 warps)
    int wid = tid >> 5, lane = tid & 31;
    for (int t = wid; t < WIN; t += 12) {
        bf162* row = (bf162*)(p + t * WIN);      // 98 pairs, 4B-aligned
        float mx = -1e30f;
        for (int j = lane; j < WIN / 2; j += 32) {
            float2 f = __bfloat1622float2(row[j]);
            mx = fmaxf(mx, fmaxf(f.x, f.y));
        }
#pragma unroll
        for (int o = 16; o > 0; o >>= 1) mx = fmaxf(mx, __shfl_xor_sync(0xffffffffu, mx, o));
        float sum = 0.0f;
        for (int j = lane; j < WIN / 2; j += 32) {
            float2 f = __bfloat1622float2(row[j]);
            float e0 = __expf(f.x - mx), e1 = __expf(f.y - mx);
            row[j] = __floats2bfloat162_rn(e0, e1);
            sum += e0 + e1;
        }
#pragma unroll
        for (int o = 16; o > 0; o >>= 1) sum += __shfl_xor_sync(0xffffffffu, sum, o);
        if (lane == 0) sInv[t] = 1.0f / sum;
    }
    __syncthreads();

    // AV: unit = 4 targets x 6 channels; 49*4 = 196 units (chg = tid&3 for bank behavior)
    if (tid < 196) {
        int chg = tid & 3, tgrp = tid >> 2;      // tgrp 0..48
        int t0 = tgrp * 4, c0 = chg * 6;
        float acc[6][4];
#pragma unroll
        for (int c = 0; c < 6; c++)
#pragma unroll
            for (int i = 0; i < 4; i++) acc[c][i] = 0.0f;
        for (int s4 = 0; s4 < WIN / 4; s4++) {
            float2 pv[4][2];
#pragma unroll
            for (int i = 0; i < 4; i++) {
                uint2 u = *(const uint2*)(p + (t0 + i) * WIN + s4 * 4);
                pv[i][0] = __bfloat1622float2(*(const bf162*)&u.x);
                pv[i][1] = __bfloat1622float2(*(const bf162*)&u.y);
            }
#pragma unroll
            for (int c = 0; c < 6; c++) {
                uint2 u = *(const uint2*)(v + (c0 + c) * WIN + s4 * 4);
                float2 v0 = __bfloat1622float2(*(const bf162*)&u.x);
                float2 v1 = __bfloat1622float2(*(const bf162*)&u.y);
#pragma unroll
                for (int i = 0; i < 4; i++) {
                    acc[c][i] = fmaf(v0.x, pv[i][0].x, acc[c][i]);
                    acc[c][i] = fmaf(v0.y, pv[i][0].y, acc[c][i]);
                    acc[c][i] = fmaf(v1.x, pv[i][1].x, acc[c][i]);
                    acc[c][i] = fmaf(v1.y, pv[i][1].y, acc[c][i]);
                }
            }
        }
#pragma unroll
        for (int i = 0; i < 4; i++) {
            int t = t0 + i, n;
            if (branch == 0) { int h = t / 7, ww = t % 7; n = h * RESO + wi * 7 + ww; }
            else             { int h = t / 28, ww = t % 28; n = (wi * 7 + h) * RESO + ww; }
            float si = sInv[t];
            size_t base = ((size_t)b * NTOK + n) * DIMC + coff + c0;
#pragma unroll
            for (int c = 0; c < 6; c += 2)
                *(bf162*)(attn + base + c) =
                    __floats2bfloat162_rn(acc[c][i] * si, acc[c + 1][i] * si);
        }
    }
}

// ---------------- launch ----------------
extern "C" void kernel_launch(void* const* d_in, const int* in_sizes, int n_in,
                              void* d_out, int out_size) {
    const float* x   = (const float*)d_in[0];
    const float* n1w = (const float*)d_in[1];
    const float* n1b = (const float*)d_in[2];
    const float* n2w = (const float*)d_in[3];
    const float* n2b = (const float*)d_in[4];
    const float* c0w = (const float*)d_in[5];
    const float* c0b = (const float*)d_in[6];
    const float* g0w = (const float*)d_in[7];
    const float* g0b = (const float*)d_in[8];
    const float* c1w = (const float*)d_in[9];
    const float* c1b = (const float*)d_in[10];
    const float* g1w = (const float*)d_in[11];
    const float* g1b = (const float*)d_in[12];
    const float* pw  = (const float*)d_in[13];
    const float* pb  = (const float*)d_in[14];
    const float* f1w = (const float*)d_in[15];
    const float* f1b = (const float*)d_in[16];
    const float* f2w = (const float*)d_in[17];
    const float* f2b = (const float*)d_in[18];
    const float* a1  = (const float*)d_in[19];
    const float* a2  = (const float*)d_in[20];
    float* out = (float*)d_out;

    float *an, *xmid, *gbp0, *gbp1;
    bf16 *wv0, *wv1, *logits, *attn, *mn, *h, *bw0, *bw1, *bpw, *bf1, *bf2;
    cudaGetSymbolAddress((void**)&an, g_an);
    cudaGetSymbolAddress((void**)&wv0, g_wv0);
    cudaGetSymbolAddress((void**)&wv1, g_wv1);
    cudaGetSymbolAddress((void**)&logits, g_logits);
    cudaGetSymbolAddress((void**)&attn, g_attn);
    cudaGetSymbolAddress((void**)&xmid, g_xmid);
    cudaGetSymbolAddress((void**)&mn, g_mn);
    cudaGetSymbolAddress((void**)&h, g_h);
    cudaGetSymbolAddress((void**)&bw0, g_bw0);
    cudaGetSymbolAddress((void**)&bw1, g_bw1);
    cudaGetSymbolAddress((void**)&bpw, g_bpw);
    cudaGetSymbolAddress((void**)&bf1, g_bf1);
    cudaGetSymbolAddress((void**)&bf2, g_bf2);
    cudaGetSymbolAddress((void**)&gbp0, g_gbp0);
    cudaGetSymbolAddress((void**)&gbp1, g_gbp1);

    int smix = (WIN * WIN + CHH * WIN) * 2 + WIN * 4; // 87024 B
    cudaFuncSetAttribute(kmix, cudaFuncAttributeMaxDynamicSharedMemorySize, smix);

    // weight conversions / permutes
    int n4;
    dim3 t328(32, 8);
    kcvtp<<<dim3(7, 7, KGEN), t328>>>(g0w, bw0);
    kcvtp<<<dim3(7, 7, KGEN), t328>>>(g1w, bw1);
    kpbias<<<(NGEN + 255) / 256, 256>>>(g0b, gbp0);
    kpbias<<<(NGEN + 255) / 256, 256>>>(g1b, gbp1);
    n4 = DIMC * DIMC / 4; kcvt<<<(n4 + 255) / 256, 256>>>(pw, bpw, n4);
    n4 = DIMC * HID / 4;  kcvt<<<(n4 + 255) / 256, 256>>>(f1w, bf1, n4);
    n4 = HID * DIMC / 4;  kcvt<<<(n4 + 255) / 256, 256>>>(f2w, bf2, n4);

    // fused norm1 + compress, pad wv
    knormc<<<MTOK, 128>>>(x, n1w, n1b, c0w, c0b, c1w, c1b, an, wv0, wv1);
    kpad<<<MGEN, 32>>>(wv0, wv1);

    // branch 0: logits GEMM (t-major out) + mix
    dim3 gl((NGEN + 127) / 128, MGEN / 128);
    tgemm<0, bf16><<<gl, 256>>>(wv0, bw0, gbp0, nullptr, nullptr, logits, KGENP, KGEN, NGEN);
    kmix<<<MGEN, 384, smix>>>(logits, an, attn, 0);
    // branch 1
    tgemm<0, bf16><<<gl, 256>>>(wv1, bw1, gbp1, nullptr, nullptr, logits, KGENP, KGEN, NGEN);
    kmix<<<MGEN, 384, smix>>>(logits, an, attn, 1);

    // proj + alpha1 residual (fp32 out)
    dim3 gp(DIMC / 128, MTOK / 128);
    tgemm<2, float><<<gp, 256>>>(attn, bpw, pb, x, a1, xmid, DIMC, DIMC, DIMC);
    // norm2 (bf16 out)
    knorm<bf16><<<MTOK, 128>>>(xmid, n2w, n2b, mn);
    // fc1 + GELU (bf16 out)
    dim3 gf1(HID / 128, MTOK / 128);
    tgemm<1, bf16><<<gf1, 256>>>(mn, bf1, f1b, nullptr, nullptr, h, DIMC, DIMC, HID);
    // fc2 + alpha2 residual -> out (fp32)
    tgemm<2, float><<<gp, 256>>>(h, bf2, f2b, xmid, a2, out, HID, HID, DIMC);
}

// round 7
// speedup vs baseline: 1.0401x; 1.0401x over previous
#include <cuda_runtime.h>
#include <cuda_bf16.h>
#include <math.h>
#include <stdint.h>

// ---------------- problem constants ----------------
#define BATCH   64
#define RESO    28
#define NTOK    784
#define DIMC    384
#define CBR     192
#define HEADS   8
#define CHH     24
#define WIN     196
#define GPB     32
#define HID     1536
#define MTOK    (BATCH*NTOK)   // 50176
#define MGEN    (BATCH*GPB)    // 2048
#define KGEN    392
#define KGENP   416
#define NGEN    38416
#define PST     216            // kmix SMEM row stride (bf16): 432B, 16B-mult, conflict-free

typedef __nv_bfloat16 bf16;
typedef __nv_bfloat162 bf162;

// ---------------- scratch ----------------
__device__ __align__(16) float g_an[(size_t)MTOK*DIMC];
__device__ __align__(16) bf16  g_wv0[(size_t)MGEN*KGENP];
__device__ __align__(16) bf16  g_wv1[(size_t)MGEN*KGENP];
__device__ __align__(16) bf16  g_logits[(size_t)2*MGEN*NGEN];
__device__ __align__(16) bf16  g_attn[(size_t)MTOK*DIMC];
__device__ __align__(16) float g_xmid[(size_t)MTOK*DIMC];
__device__ __align__(16) bf16  g_mn[(size_t)MTOK*DIMC];
__device__ __align__(16) bf16  g_h[(size_t)MTOK*HID];
__device__ __align__(16) bf16  g_bw0[(size_t)KGEN*NGEN];   // t-major permuted
__device__ __align__(16) bf16  g_bw1[(size_t)KGEN*NGEN];
__device__ __align__(16) bf16  g_bpw[(size_t)DIMC*DIMC];
__device__ __align__(16) bf16  g_bf1[(size_t)DIMC*HID];
__device__ __align__(16) bf16  g_bf2[(size_t)HID*DIMC];
__device__ __align__(16) float g_gbp0[NGEN];
__device__ __align__(16) float g_gbp1[NGEN];

// ---------------- helpers ----------------
__device__ __forceinline__ uint32_t smem_u32(const void* p) {
    uint32_t a;
    asm("{ .reg .u64 t; cvta.to.shared.u64 t, %1; cvt.u32.u64 %0, t; }" : "=r"(a) : "l"(p));
    return a;
}
__device__ __forceinline__ void cp16(uint32_t d, const void* s, uint32_t sz) {
    asm volatile("cp.async.cg.shared.global [%0], [%1], 16, %2;" :: "r"(d), "l"(s), "r"(sz));
}
#define CP_COMMIT() asm volatile("cp.async.commit_group;" ::: "memory")
#define CP_WAIT(n)  asm volatile("cp.async.wait_group %0;" :: "n"(n) : "memory")

__device__ __forceinline__ void mma16(float* d, const uint32_t* a, const uint32_t* b) {
    asm volatile(
        "mma.sync.aligned.m16n8k16.row.col.f32.bf16.bf16.f32 "
        "{%0,%1,%2,%3},{%4,%5,%6,%7},{%8,%9},{%0,%1,%2,%3};"
        : "+f"(d[0]), "+f"(d[1]), "+f"(d[2]), "+f"(d[3])
        : "r"(a[0]), "r"(a[1]), "r"(a[2]), "r"(a[3]), "r"(b[0]), "r"(b[1]));
}
__device__ __forceinline__ void ldsm4(uint32_t* r, uint32_t addr) {
    asm volatile("ldmatrix.sync.aligned.m8n8.x4.shared.b16 {%0,%1,%2,%3}, [%4];"
        : "=r"(r[0]), "=r"(r[1]), "=r"(r[2]), "=r"(r[3]) : "r"(addr));
}
__device__ __forceinline__ void ldsm4t(uint32_t* r, uint32_t addr) {
    asm volatile("ldmatrix.sync.aligned.m8n8.x4.trans.shared.b16 {%0,%1,%2,%3}, [%4];"
        : "=r"(r[0]), "=r"(r[1]), "=r"(r[2]), "=r"(r[3]) : "r"(addr));
}
__device__ __forceinline__ void ldsm2(uint32_t* r, uint32_t addr) {
    asm volatile("ldmatrix.sync.aligned.m8n8.x2.shared.b16 {%0,%1}, [%2];"
        : "=r"(r[0]), "=r"(r[1]) : "r"(addr));
}

template <typename T>
__device__ __forceinline__ void st2(T* C, size_t idx, float v0, float v1);
template <>
__device__ __forceinline__ void st2<float>(float* C, size_t idx, float v0, float v1) {
    *(float2*)(C + idx) = make_float2(v0, v1);
}
template <>
__device__ __forceinline__ void st2<bf16>(bf16* C, size_t idx, float v0, float v1) {
    *(bf162*)(C + idx) = __floats2bfloat162_rn(v0, v1);
}

// ---------------- fp32 -> bf16 weight convert ----------------
__global__ void kcvt(const float* __restrict__ s, bf16* __restrict__ d, int n4) {
    int i = blockIdx.x * blockDim.x + threadIdx.x;
    if (i < n4) {
        float4 f = ((const float4*)s)[i];
        bf162* dd = (bf162*)d;
        dd[i * 2]     = __floats2bfloat162_rn(f.x, f.y);
        dd[i * 2 + 1] = __floats2bfloat162_rn(f.z, f.w);
    }
}

// ---------------- generate-weight convert + column permute (s,t)->(t,s) ----------------
__global__ void kcvtp(const float* __restrict__ W, bf16* __restrict__ Wp) {
    __shared__ float tile[32][33];
    int k = blockIdx.z;
    int s0 = blockIdx.y * 32, t0 = blockIdx.x * 32;
    int tx = threadIdx.x, ty = threadIdx.y; // 32 x 8
    const float* src = W + (size_t)k * NGEN;
    bf16* dst = Wp + (size_t)k * NGEN;
    for (int i = ty; i < 32; i += 8) {
        int s = s0 + i, t = t0 + tx;
        tile[i][tx] = (s < WIN && t < WIN) ? src[s * WIN + t] : 0.0f;
    }
    __syncthreads();
    for (int i = ty; i < 32; i += 8) {
        int t = t0 + i, s = s0 + tx;
        if (t < WIN && s < WIN)
            dst[t * WIN + s] = __float2bfloat16(tile[tx][i]);
    }
}

__global__ void kpbias(const float* __restrict__ b, float* __restrict__ bp) {
    int i = blockIdx.x * blockDim.x + threadIdx.x;
    if (i < NGEN) {
        int t = i / WIN, s = i % WIN;
        bp[i] = b[s * WIN + t];
    }
}

// ---------------- fused center-norm1 + compress ----------------
__global__ __launch_bounds__(128) void knormc(
    const float* __restrict__ x, const float* __restrict__ w, const float* __restrict__ bb,
    const float* __restrict__ c0w, const float* __restrict__ c0b,
    const float* __restrict__ c1w, const float* __restrict__ c1b,
    float* __restrict__ an, bf16* __restrict__ wv0, bf16* __restrict__ wv1) {
    int tok = blockIdx.x;
    int b = tok / NTOK, n = tok % NTOK;
    const float* xr = x + (size_t)tok * DIMC;
    float* orow = an + (size_t)tok * DIMC;
    int tid = threadIdx.x;
    __shared__ float xs[DIMC];
    __shared__ float red[4];
    __shared__ float partial[4][32];

    float v0 = xr[tid], v1 = xr[tid + 128], v2 = xr[tid + 256];
    float s = v0 + v1 + v2;
#pragma unroll
    for (int o = 16; o > 0; o >>= 1) s += __shfl_xor_sync(0xffffffffu, s, o);
    if ((tid & 31) == 0) red[tid >> 5] = s;
    __syncthreads();
    float u = (red[0] + red[1] + red[2] + red[3]) * (1.0f / DIMC);
    const float sc = (float)DIMC / (float)(DIMC - 1);
    float o0 = w[tid]       * (sc * (v0 - u)) + bb[tid];
    float o1 = w[tid + 128] * (sc * (v1 - u)) + bb[tid + 128];
    float o2 = w[tid + 256] * (sc * (v2 - u)) + bb[tid + 256];
    orow[tid] = o0; orow[tid + 128] = o1; orow[tid + 256] = o2;
    xs[tid] = o0; xs[tid + 128] = o1; xs[tid + 256] = o2;
    __syncthreads();

    int o = tid & 31, chunk = tid >> 5;
    int branch = o >> 4, j = o & 15;
    const float* cw = branch ? c1w : c0w;
    const float* xb = xs + branch * CBR;
    float acc = 0.0f;
    int k0 = chunk * 48;
#pragma unroll 4
    for (int k = k0; k < k0 + 48; k++) acc = fmaf(xb[k], cw[k * 16 + j], acc);
    partial[chunk][o] = acc;
    __syncthreads();
    if (tid < 32) {
        int oo = tid;
        int br = oo >> 4, jj = oo & 15;
        float sum = partial[0][oo] + partial[1][oo] + partial[2][oo] + partial[3][oo]
                  + (br ? c1b[jj] : c0b[jj]);
        int head = jj >> 1, di = jj & 1;
        int row = n / RESO, col = n % RESO;
        int g, ss;
        if (br == 0) { int n2i = col / 7; g = n2i * HEADS + head; ss = row * 7 + col % 7; }
        else         { int n1i = row / 7; g = n1i * HEADS + head; ss = (row % 7) * 28 + col; }
        bf16* dst = br ? wv1 : wv0;
        dst[(size_t)(b * GPB + g) * KGENP + ss * 2 + di] = __float2bfloat16(sum);
    }
}

__global__ void kpad(bf16* __restrict__ wv0, bf16* __restrict__ wv1) {
    int r = blockIdx.x, t = threadIdx.x;
    if (t < KGENP - KGEN) {
        wv0[(size_t)r * KGENP + KGEN + t] = __float2bfloat16(0.0f);
        wv1[(size_t)r * KGENP + KGEN + t] = __float2bfloat16(0.0f);
    }
}

// ---------------- center norm (stage 2) ----------------
template <typename OUTT>
__global__ void knorm(const float* __restrict__ x, const float* __restrict__ w,
                      const float* __restrict__ bb, OUTT* __restrict__ out) {
    int t = blockIdx.x;
    const float* xr = x + (size_t)t * DIMC;
    OUTT* orow = out + (size_t)t * DIMC;
    int tid = threadIdx.x; // 128
    float v0 = xr[tid], v1 = xr[tid + 128], v2 = xr[tid + 256];
    float s = v0 + v1 + v2;
#pragma unroll
    for (int o = 16; o > 0; o >>= 1) s += __shfl_xor_sync(0xffffffffu, s, o);
    __shared__ float red[4];
    if ((tid & 31) == 0) red[tid >> 5] = s;
    __syncthreads();
    float u = (red[0] + red[1] + red[2] + red[3]) * (1.0f / DIMC);
    const float sc = (float)DIMC / (float)(DIMC - 1);
    orow[tid]       = (OUTT)(w[tid]       * (sc * (v0 - u)) + bb[tid]);
    orow[tid + 128] = (OUTT)(w[tid + 128] * (sc * (v1 - u)) + bb[tid + 128]);
    orow[tid + 256] = (OUTT)(w[tid + 256] * (sc * (v2 - u)) + bb[tid + 256]);
}

// ---------------- bf16 mma.sync GEMM, 2-stage pipeline ----------------
// DUAL: blockIdx.z selects {A,B,bias,C} pair (logits branches in one launch).
template <int EPI, typename OUTT, bool DUAL>
__global__ __launch_bounds__(256, 2) void tgemm(
    const bf16* __restrict__ A, const bf16* __restrict__ B,
    const float* __restrict__ bias, const float* __restrict__ res,
    const float* __restrict__ alpha, OUTT* __restrict__ C,
    const bf16* A1, const bf16* B1, const float* bias1, OUTT* C1,
    int lda, int Kreal, int NC) {
    if (DUAL && blockIdx.z == 1) { A = A1; B = B1; bias = bias1; C = C1; }
    __shared__ bf16 As[2][128][40];
    __shared__ bf16 Bs[2][32][136];

    int tid = threadIdx.x;
    int w = tid >> 5, lane = tid & 31;
    int warpM = w >> 2, warpN = w & 3;
    int lr = lane >> 2, lc = lane & 3;
    int row0 = blockIdx.y * 128, col0 = blockIdx.x * 128;
    const int S = lda / 32;

    float acc[4][4][4];
#pragma unroll
    for (int a = 0; a < 4; a++)
#pragma unroll
        for (int bq = 0; bq < 4; bq++)
#pragma unroll
            for (int cq = 0; cq < 4; cq++) acc[a][bq][cq] = 0.0f;

    auto load_stage = [&](int s, int buf) {
        int s32 = s * 32;
#pragma unroll
        for (int i = 0; i < 2; i++) {
            int idx = tid + i * 256;
            int r = idx >> 2, c = idx & 3;
            cp16(smem_u32(&As[buf][r][c * 8]),
                 A + (size_t)(row0 + r) * lda + s32 + c * 8, 16u);
        }
#pragma unroll
        for (int i = 0; i < 2; i++) {
            int idx = tid + i * 256;
            int k = idx >> 4, c = idx & 15;
            int krow = s32 + k, gc = col0 + c * 8;
            bool val = (krow < Kreal) && (gc < NC);
            const bf16* sp = val ? (B + (size_t)krow * NC + gc) : B;
            cp16(smem_u32(&Bs[buf][k][c * 8]), sp, val ? 16u : 0u);
        }
    };

    load_stage(0, 0);
    CP_COMMIT();

    for (int s = 0; s < S; s++) {
        int cur = s & 1;
        if (s + 1 < S) {
            load_stage(s + 1, cur ^ 1);
            CP_COMMIT();
            CP_WAIT(1);
        } else {
            CP_WAIT(0);
        }
        __syncthreads();

#pragma unroll
        for (int ks = 0; ks < 2; ks++) {
            uint32_t ar[4][4];
            uint32_t br[4][2];
            int m = lane >> 3;
            int rA8 = (m & 1) * 8 + (lane & 7);
            int cA = ks * 16 + (m >> 1) * 8;
#pragma unroll
            for (int mt = 0; mt < 4; mt++)
                ldsm4(ar[mt], smem_u32(&As[cur][warpM * 64 + mt * 16 + rA8][cA]));
            int kB = ks * 16 + ((lane >> 3) & 1) * 8 + (lane & 7);
            int nB8 = (lane >> 4) * 8;
#pragma unroll
            for (int np = 0; np < 2; np++) {
                uint32_t rr[4];
                ldsm4t(rr, smem_u32(&Bs[cur][kB][warpN * 32 + np * 16 + nB8]));
                br[np * 2][0] = rr[0]; br[np * 2][1] = rr[1];
                br[np * 2 + 1][0] = rr[2]; br[np * 2 + 1][1] = rr[3];
            }
#pragma unroll
            for (int mt = 0; mt < 4; mt++)
#pragma unroll
                for (int nt = 0; nt < 4; nt++)
                    mma16(acc[mt][nt], ar[mt], br[nt]);
        }
        __syncthreads();
    }

#pragma unroll
    for (int mt = 0; mt < 4; mt++) {
#pragma unroll
        for (int nt = 0; nt < 4; nt++) {
            int cbase = col0 + warpN * 32 + nt * 8 + lc * 2;
            if (cbase >= NC) continue;
            float bi0 = bias[cbase], bi1 = bias[cbase + 1];
            float al0 = 0.f, al1 = 0.f;
            if (EPI == 2) { al0 = alpha[cbase]; al1 = alpha[cbase + 1]; }
#pragma unroll
            for (int hh = 0; hh < 2; hh++) {
                int r = row0 + warpM * 64 + mt * 16 + lr + hh * 8;
                float v0 = acc[mt][nt][hh * 2]     + bi0;
                float v1 = acc[mt][nt][hh * 2 + 1] + bi1;
                size_t idx = (size_t)r * NC + cbase;
                if (EPI == 1) {
                    v0 = 0.5f * v0 * (1.0f + erff(v0 * 0.70710678118654752f));
                    v1 = 0.5f * v1 * (1.0f + erff(v1 * 0.70710678118654752f));
                }
                if (EPI == 2) {
                    float2 rr = *(const float2*)(res + idx);
                    v0 = rr.x + al0 * v0;
                    v1 = rr.y + al1 * v1;
                }
                st2<OUTT>(C, idx, v0, v1);
            }
        }
    }
}

// ---------------- fused softmax + HMMA AV + scatter ----------------
// grid = 2*MGEN; t-major logits (both branches). Per block: one (branch, bg) window.
__global__ __launch_bounds__(256, 2) void kmix(const bf16* __restrict__ logits,
                                               const float* __restrict__ an,
                                               bf16* __restrict__ attn) {
    extern __shared__ char smb[];
    bf16* p = (bf16*)smb;                           // [208][PST]
    bf16* v = (bf16*)(smb + 208 * PST * 2);         // [24][PST]
    float* sInv = (float*)(smb + (208 + 24) * PST * 2); // [196]

    int blk = blockIdx.x;
    int branch = blk >> 11;         // MGEN = 2048
    int bg = blk & 2047;
    int b = bg / GPB, g = bg % GPB;
    int head = g % HEADS, wi = g / HEADS;
    int coff = branch * CBR + head * CHH;
    int tid = threadIdx.x;
    const bf16* lg = logits + ((size_t)branch * MGEN + bg) * NGEN;

    // copy logits rows into padded SMEM (49 uint2 per row)
    for (int i = tid; i < WIN * 49; i += 256) {
        int t = i / 49, j = i % 49;
        *(uint2*)(p + t * PST + j * 4) = *(const uint2*)(lg + t * WIN + j * 4);
    }
    // zero k-pad columns of p (cols 196..215, rows 0..207)
    for (int i = tid; i < 208 * 20; i += 256) {
        int t = i / 20, c = WIN + i % 20;
        p[t * PST + c] = __float2bfloat16(0.0f);
    }
    // v gather (bf16), zero k-pad
    for (int i = tid; i < CHH * PST; i += 256) {
        int c = i / PST, s = i % PST;
        float val = 0.0f;
        if (s < WIN) {
            int n;
            if (branch == 0) { int h = s / 7, ww = s % 7; n = h * RESO + wi * 7 + ww; }
            else             { int h = s / 28, ww = s % 28; n = (wi * 7 + h) * RESO + ww; }
            val = an[((size_t)b * NTOK + n) * DIMC + coff + c];
        }
        v[c * PST + s] = __float2bfloat16(val);
    }
    __syncthreads();

    // softmax over contiguous s: warp per row t
    int w = tid >> 5, lane = tid & 31;
    for (int t = w; t < WIN; t += 8) {
        bf162* row = (bf162*)(p + t * PST);   // 98 pairs
        float mx = -1e30f;
        for (int j = lane; j < WIN / 2; j += 32) {
            float2 f = __bfloat1622float2(row[j]);
            mx = fmaxf(mx, fmaxf(f.x, f.y));
        }
#pragma unroll
        for (int o = 16; o > 0; o >>= 1) mx = fmaxf(mx, __shfl_xor_sync(0xffffffffu, mx, o));
        float sum = 0.0f;
        for (int j = lane; j < WIN / 2; j += 32) {
            float2 f = __bfloat1622float2(row[j]);
            float e0 = __expf(f.x - mx), e1 = __expf(f.y - mx);
            row[j] = __floats2bfloat162_rn(e0, e1);
            sum += e0 + e1;
        }
#pragma unroll
        for (int o = 16; o > 0; o >>= 1) sum += __shfl_xor_sync(0xffffffffu, sum, o);
        if (lane == 0) sInv[t] = 1.0f / sum;
    }
    __syncthreads();

    // AV via HMMA: C(196t x 24c) = P @ V^T; 13 m-tiles x 3 n-tiles, k = 13 x 16
    uint32_t pbase = smem_u32(p);
    uint32_t vbase = smem_u32(v);
    for (int u = w; u < 39; u += 8) {
        int mt = u % 13, nt = u / 13;
        float c4[4] = {0.f, 0.f, 0.f, 0.f};
        uint32_t aaddr = pbase
            + (uint32_t)((mt * 16 + ((lane >> 3) & 1) * 8 + (lane & 7)) * PST + (lane >> 4) * 8) * 2;
        uint32_t baddr = vbase
            + (uint32_t)((nt * 8 + (lane & 7)) * PST + ((lane >> 3) & 1) * 8) * 2;
#pragma unroll
        for (int k = 0; k < 13; k++) {
            uint32_t a[4], bb[2];
            ldsm4(a, aaddr + k * 32);
            ldsm2(bb, baddr + k * 32);
            mma16(c4, a, bb);
        }
        int r0 = mt * 16 + (lane >> 2);
        int n0 = nt * 8 + (lane & 3) * 2;
#pragma unroll
        for (int hh = 0; hh < 2; hh++) {
            int t = r0 + hh * 8;
            if (t < WIN) {
                float si = sInv[t];
                int n;
                if (branch == 0) { int h = t / 7, ww = t % 7; n = h * RESO + wi * 7 + ww; }
                else             { int h = t / 28, ww = t % 28; n = (wi * 7 + h) * RESO + ww; }
                size_t base = ((size_t)b * NTOK + n) * DIMC + coff + n0;
                *(bf162*)(attn + base) =
                    __floats2bfloat162_rn(c4[hh * 2] * si, c4[hh * 2 + 1] * si);
            }
        }
    }
}

// ---------------- launch ----------------
extern "C" void kernel_launch(void* const* d_in, const int* in_sizes, int n_in,
                              void* d_out, int out_size) {
    const float* x   = (const float*)d_in[0];
    const float* n1w = (const float*)d_in[1];
    const float* n1b = (const float*)d_in[2];
    const float* n2w = (const float*)d_in[3];
    const float* n2b = (const float*)d_in[4];
    const float* c0w = (const float*)d_in[5];
    const float* c0b = (const float*)d_in[6];
    const float* g0w = (const float*)d_in[7];
    const float* g0b = (const float*)d_in[8];
    const float* c1w = (const float*)d_in[9];
    const float* c1b = (const float*)d_in[10];
    const float* g1w = (const float*)d_in[11];
    const float* g1b = (const float*)d_in[12];
    const float* pw  = (const float*)d_in[13];
    const float* pb  = (const float*)d_in[14];
    const float* f1w = (const float*)d_in[15];
    const float* f1b = (const float*)d_in[16];
    const float* f2w = (const float*)d_in[17];
    const float* f2b = (const float*)d_in[18];
    const float* a1  = (const float*)d_in[19];
    const float* a2  = (const float*)d_in[20];
    float* out = (float*)d_out;

    float *an, *xmid, *gbp0, *gbp1;
    bf16 *wv0, *wv1, *logits, *attn, *mn, *h, *bw0, *bw1, *bpw, *bf1, *bf2;
    cudaGetSymbolAddress((void**)&an, g_an);
    cudaGetSymbolAddress((void**)&wv0, g_wv0);
    cudaGetSymbolAddress((void**)&wv1, g_wv1);
    cudaGetSymbolAddress((void**)&logits, g_logits);
    cudaGetSymbolAddress((void**)&attn, g_attn);
    cudaGetSymbolAddress((void**)&xmid, g_xmid);
    cudaGetSymbolAddress((void**)&mn, g_mn);
    cudaGetSymbolAddress((void**)&h, g_h);
    cudaGetSymbolAddress((void**)&bw0, g_bw0);
    cudaGetSymbolAddress((void**)&bw1, g_bw1);
    cudaGetSymbolAddress((void**)&bpw, g_bpw);
    cudaGetSymbolAddress((void**)&bf1, g_bf1);
    cudaGetSymbolAddress((void**)&bf2, g_bf2);
    cudaGetSymbolAddress((void**)&gbp0, g_gbp0);
    cudaGetSymbolAddress((void**)&gbp1, g_gbp1);

    int smix = (208 + 24) * PST * 2 + WIN * 4;  // 101,008 B
    cudaFuncSetAttribute(kmix, cudaFuncAttributeMaxDynamicSharedMemorySize, smix);

    // weight conversions / permutes
    int n4;
    dim3 t328(32, 8);
    kcvtp<<<dim3(7, 7, KGEN), t328>>>(g0w, bw0);
    kcvtp<<<dim3(7, 7, KGEN), t328>>>(g1w, bw1);
    kpbias<<<(NGEN + 255) / 256, 256>>>(g0b, gbp0);
    kpbias<<<(NGEN + 255) / 256, 256>>>(g1b, gbp1);
    n4 = DIMC * DIMC / 4; kcvt<<<(n4 + 255) / 256, 256>>>(pw, bpw, n4);
    n4 = DIMC * HID / 4;  kcvt<<<(n4 + 255) / 256, 256>>>(f1w, bf1, n4);
    n4 = HID * DIMC / 4;  kcvt<<<(n4 + 255) / 256, 256>>>(f2w, bf2, n4);

    // fused norm1 + compress, pad wv
    knormc<<<MTOK, 128>>>(x, n1w, n1b, c0w, c0b, c1w, c1b, an, wv0, wv1);
    kpad<<<MGEN, 32>>>(wv0, wv1);

    // logits GEMM, both branches in one launch (grid.z = 2)
    dim3 gl((NGEN + 127) / 128, MGEN / 128, 2);
    tgemm<0, bf16, true><<<gl, 256>>>(wv0, bw0, gbp0, nullptr, nullptr, logits,
                                      wv1, bw1, gbp1, logits + (size_t)MGEN * NGEN,
                                      KGENP, KGEN, NGEN);
    // mix, both branches
    kmix<<<2 * MGEN, 256, smix>>>(logits, an, attn);

    // proj + alpha1 residual (fp32 out)
    dim3 gp(DIMC / 128, MTOK / 128);
    tgemm<2, float, false><<<gp, 256>>>(attn, bpw, pb, x, a1, xmid,
                                        nullptr, nullptr, nullptr, nullptr,
                                        DIMC, DIMC, DIMC);
    // norm2 (bf16 out)
    knorm<bf16><<<MTOK, 128>>>(xmid, n2w, n2b, mn);
    // fc1 + GELU (bf16 out)
    dim3 gf1(HID / 128, MTOK / 128);
    tgemm<1, bf16, false><<<gf1, 256>>>(mn, bf1, f1b, nullptr, nullptr, h,
                                        nullptr, nullptr, nullptr, nullptr,
                                        DIMC, DIMC, HID);
    // fc2 + alpha2 residual -> out (fp32)
    tgemm<2, float, false><<<gp, 256>>>(h, bf2, f2b, xmid, a2, out,
                                        nullptr, nullptr, nullptr, nullptr,
                                        HID, HID, DIMC);
}